// round 8
// baseline (speedup 1.0000x reference)
#include <cuda_runtime.h>
#include <cuda_bf16.h>
#include <math.h>

#define NMAX 50000
#define EMAX 600000
#define DIM 128

// ---------------- scratch (device globals; no allocations allowed) ----------------
__device__ float g_q[NMAX * DIM];
__device__ float g_k[NMAX * DIM];
__device__ float g_v[NMAX * DIM];
__device__ float g_s[NMAX * DIM];
__device__ float g_h[NMAX * DIM];
__device__ float g_agg[NMAX * DIM];
__device__ float g_score[EMAX * 8];
__device__ float g_den[NMAX * 8];
__device__ unsigned g_smax[NMAX * 8];

// order-preserving float<->uint encoding for atomicMax on floats (incl. negatives)
__device__ __forceinline__ unsigned enc_f(float x) {
    unsigned s = __float_as_uint(x);
    unsigned mask = (unsigned)((int)s >> 31) | 0x80000000u;
    return s ^ mask;
}
__device__ __forceinline__ float dec_f(unsigned kk) {
    unsigned s = (kk & 0x80000000u) ? (kk ^ 0x80000000u) : ~kk;
    return __uint_as_float(s);
}

// ---------------- node GEMM: out[M,128] = A[M,128] @ W[128,128] + b ----------------
__global__ __launch_bounds__(256) void gemm_qkvs(
    const float* __restrict__ A, int M,
    const float* __restrict__ W0, const float* __restrict__ W1,
    const float* __restrict__ W2, const float* __restrict__ W3,
    const float* __restrict__ b0, const float* __restrict__ b1,
    const float* __restrict__ b2, const float* __restrict__ b3,
    float* __restrict__ o0, float* __restrict__ o1,
    float* __restrict__ o2, float* __restrict__ o3)
{
    const float* W; const float* bias; float* O;
    switch (blockIdx.y) {
        case 0: W = W0; bias = b0; O = o0; break;
        case 1: W = W1; bias = b1; O = o1; break;
        case 2: W = W2; bias = b2; O = o2; break;
        default: W = W3; bias = b3; O = o3; break;
    }
    __shared__ float As[8][128];
    __shared__ float Bs[8][128];
    int tid = threadIdx.x;
    int tx = tid % 16, ty = tid / 16;
    int m0 = blockIdx.x * 128;

    float acc[8][8];
#pragma unroll
    for (int i = 0; i < 8; i++)
#pragma unroll
        for (int j = 0; j < 8; j++) acc[i][j] = 0.f;

    for (int k0 = 0; k0 < 128; k0 += 8) {
        {
            int row_l = tid >> 1;
            int kk = (tid & 1) * 4;
            int row = m0 + row_l;
            float4 av = make_float4(0.f, 0.f, 0.f, 0.f);
            if (row < M) av = *reinterpret_cast<const float4*>(A + (size_t)row * 128 + k0 + kk);
            As[kk + 0][row_l] = av.x;
            As[kk + 1][row_l] = av.y;
            As[kk + 2][row_l] = av.z;
            As[kk + 3][row_l] = av.w;
        }
        {
            float4 bv = *reinterpret_cast<const float4*>(W + (size_t)k0 * 128 + tid * 4);
            int bkk = (tid * 4) >> 7;
            int bn = (tid * 4) & 127;
            Bs[bkk][bn + 0] = bv.x;
            Bs[bkk][bn + 1] = bv.y;
            Bs[bkk][bn + 2] = bv.z;
            Bs[bkk][bn + 3] = bv.w;
        }
        __syncthreads();
#pragma unroll
        for (int kk = 0; kk < 8; kk++) {
            float a[8], b[8];
#pragma unroll
            for (int i = 0; i < 8; i++) a[i] = As[kk][ty * 8 + i];
#pragma unroll
            for (int j = 0; j < 8; j++) b[j] = Bs[kk][tx * 8 + j];
#pragma unroll
            for (int i = 0; i < 8; i++)
#pragma unroll
                for (int j = 0; j < 8; j++) acc[i][j] = fmaf(a[i], b[j], acc[i][j]);
        }
        __syncthreads();
    }
#pragma unroll
    for (int i = 0; i < 8; i++) {
        int row = m0 + ty * 8 + i;
        if (row < M) {
#pragma unroll
            for (int j = 0; j < 8; j++) {
                int col = tx * 8 + j;
                O[(size_t)row * 128 + col] = acc[i][j] + bias[col];
            }
        }
    }
}

// ---------- on-the-fly edge embedding: e_row[lane*4..+3] = ea[e,:16] @ We + be ----------
// Wes: smem float4[16][32] (We transposed into lane-major float4), bes: float4[32]
__device__ __forceinline__ float4 edge_emb(
    const float* __restrict__ ea, int e, int lane,
    const float4* __restrict__ Wes, const float4* __restrict__ bes)
{
    float aval = (lane < 16) ? __ldg(ea + (size_t)e * 16 + lane) : 0.f;
    float4 acc = bes[lane];
#pragma unroll
    for (int j = 0; j < 16; j++) {
        float a = __shfl_sync(0xFFFFFFFFu, aval, j);
        float4 w = Wes[j * 32 + lane];
        acc.x = fmaf(a, w.x, acc.x);
        acc.y = fmaf(a, w.y, acc.y);
        acc.z = fmaf(a, w.z, acc.z);
        acc.w = fmaf(a, w.w, acc.w);
    }
    return acc;
}

// cooperative smem fill of We (16x128) + be (128)
__device__ __forceinline__ void load_We(
    const float* __restrict__ We, const float* __restrict__ be,
    float4* Wes, float4* bes, int tid)
{
    // 16*128 floats = 512 float4; 256 threads -> 2 each
#pragma unroll
    for (int it = 0; it < 2; it++) {
        int g = tid * 2 + it;
        Wes[g] = reinterpret_cast<const float4*>(We)[g];
    }
    if (tid < 32) bes[tid] = reinterpret_cast<const float4*>(be)[tid];
}

// ---------------- attention score + segment max (warp per edge, grid-stride) ----------------
template <int H>
__global__ __launch_bounds__(256) void score_kernel(
    const int* __restrict__ ei, int E,
    const float* __restrict__ q, const float* __restrict__ k,
    const float* __restrict__ ea,
    const float* __restrict__ We, const float* __restrict__ be,
    float* __restrict__ score, unsigned* __restrict__ smax, float scale)
{
    __shared__ float4 Wes[16 * 32];
    __shared__ float4 bes[32];
    int tid = threadIdx.x;
    load_We(We, be, Wes, bes, tid);
    __syncthreads();

    int lane = tid & 31;
    int warp0 = blockIdx.x * 8 + (tid >> 5);
    int totalWarps = gridDim.x * 8;

    for (int e = warp0; e < E; e += totalWarps) {
        int src = ei[e];
        int dst = ei[E + e];
        float4 qv = *reinterpret_cast<const float4*>(q + (size_t)dst * 128 + lane * 4);
        float4 kv = *reinterpret_cast<const float4*>(k + (size_t)src * 128 + lane * 4);
        float4 evv = edge_emb(ea, e, lane, Wes, bes);
        float s = qv.x * (kv.x + evv.x) + qv.y * (kv.y + evv.y) +
                  qv.z * (kv.z + evv.z) + qv.w * (kv.w + evv.w);
        s += __shfl_xor_sync(0xFFFFFFFFu, s, 1);
        s += __shfl_xor_sync(0xFFFFFFFFu, s, 2);
        if (H == 1) {
            s += __shfl_xor_sync(0xFFFFFFFFu, s, 4);
            s += __shfl_xor_sync(0xFFFFFFFFu, s, 8);
            s += __shfl_xor_sync(0xFFFFFFFFu, s, 16);
            s *= scale;
            if (lane == 0) {
                score[e] = s;
                atomicMax(&smax[dst], enc_f(s));
            }
        } else {  // H == 8, head = lane/4
            s *= scale;
            if ((lane & 3) == 0) {
                int h = lane >> 2;
                score[(size_t)e * 8 + h] = s;
                atomicMax(&smax[dst * 8 + h], enc_f(s));
            }
        }
    }
}

// ---------------- exp + segment denominator ----------------
template <int H>
__global__ __launch_bounds__(256) void expsum_kernel(
    const int* __restrict__ ei, int E,
    float* __restrict__ score, const unsigned* __restrict__ smax,
    float* __restrict__ den)
{
    int idx = blockIdx.x * blockDim.x + threadIdx.x;
    if (idx >= E * H) return;
    int e = (H == 1) ? idx : (idx >> 3);
    int h = (H == 1) ? 0 : (idx & 7);
    int dst = ei[E + e];
    float m = dec_f(smax[dst * H + h]);
    float ex = expf(score[idx] - m);
    score[idx] = ex;
    atomicAdd(&den[dst * H + h], ex);
}

// ---------------- message scatter (warp per edge, grid-stride) ----------------
template <int H>
__global__ __launch_bounds__(256) void scatter_kernel(
    const int* __restrict__ ei, int E,
    const float* __restrict__ v, const float* __restrict__ ea,
    const float* __restrict__ We, const float* __restrict__ be,
    const float* __restrict__ score, const float* __restrict__ den,
    float* __restrict__ agg)
{
    __shared__ float4 Wes[16 * 32];
    __shared__ float4 bes[32];
    int tid = threadIdx.x;
    load_We(We, be, Wes, bes, tid);
    __syncthreads();

    int lane = tid & 31;
    int warp0 = blockIdx.x * 8 + (tid >> 5);
    int totalWarps = gridDim.x * 8;

    for (int e = warp0; e < E; e += totalWarps) {
        int src = ei[e];
        int dst = ei[E + e];
        float alpha;
        if (H == 1) {
            alpha = score[e] / (den[dst] + 1e-16f);
        } else {
            int h = lane >> 2;
            alpha = score[(size_t)e * 8 + h] / (den[dst * 8 + h] + 1e-16f);
        }
        float4 vv = *reinterpret_cast<const float4*>(v + (size_t)src * 128 + lane * 4);
        float4 evv = edge_emb(ea, e, lane, Wes, bes);
        float* base = agg + (size_t)dst * 128 + lane * 4;
        atomicAdd(base + 0, (vv.x + evv.x) * alpha);
        atomicAdd(base + 1, (vv.y + evv.y) * alpha);
        atomicAdd(base + 2, (vv.z + evv.z) * alpha);
        atomicAdd(base + 3, (vv.w + evv.w) * alpha);
    }
}

// ---------------- epilogue: skip add (+ optional leaky relu) ----------------
template <bool RELU>
__global__ __launch_bounds__(256) void finalize_kernel(
    const float* __restrict__ agg, const float* __restrict__ skip,
    float* __restrict__ out, int n)
{
    int idx = blockIdx.x * blockDim.x + threadIdx.x;
    if (idx >= n) return;
    float val = agg[idx] + skip[idx];
    if (RELU) val = val > 0.f ? val : 0.01f * val;
    out[idx] = val;
}

extern "C" void kernel_launch(void* const* d_in, const int* in_sizes, int n_in,
                              void* d_out, int out_size) {
    const float* x  = (const float*)d_in[0];
    const int*   ei = (const int*)d_in[1];
    const float* ea = (const float*)d_in[2];
    const float* Wq1 = (const float*)d_in[3],  *bq1 = (const float*)d_in[4];
    const float* Wk1 = (const float*)d_in[5],  *bk1 = (const float*)d_in[6];
    const float* Wv1 = (const float*)d_in[7],  *bv1 = (const float*)d_in[8];
    const float* We1 = (const float*)d_in[9],  *be1 = (const float*)d_in[10];
    const float* Ws1 = (const float*)d_in[11], *bs1 = (const float*)d_in[12];
    const float* Wq2 = (const float*)d_in[13], *bq2 = (const float*)d_in[14];
    const float* Wk2 = (const float*)d_in[15], *bk2 = (const float*)d_in[16];
    const float* Wv2 = (const float*)d_in[17], *bv2 = (const float*)d_in[18];
    const float* We2 = (const float*)d_in[19], *be2 = (const float*)d_in[20];
    const float* Ws2 = (const float*)d_in[21], *bs2 = (const float*)d_in[22];

    int Nn = in_sizes[0] / DIM;
    int Ee = in_sizes[1] / 2;

    float *q, *k, *v, *s, *h, *agg, *score, *den;
    unsigned* smax;
    cudaGetSymbolAddress((void**)&q, g_q);
    cudaGetSymbolAddress((void**)&k, g_k);
    cudaGetSymbolAddress((void**)&v, g_v);
    cudaGetSymbolAddress((void**)&s, g_s);
    cudaGetSymbolAddress((void**)&h, g_h);
    cudaGetSymbolAddress((void**)&agg, g_agg);
    cudaGetSymbolAddress((void**)&score, g_score);
    cudaGetSymbolAddress((void**)&den, g_den);
    cudaGetSymbolAddress((void**)&smax, g_smax);

    dim3 gemmGrid((Nn + 127) / 128, 4);
    // grid-stride edge kernels: enough blocks for full occupancy, few enough
    // that the 8KB We smem fill amortizes over ~35+ edges per warp
    int edgeBlocks = 2048;

    // ---------------- layer 1 (heads=8, C=16) ----------------
    gemm_qkvs<<<gemmGrid, 256>>>(x, Nn, Wq1, Wk1, Wv1, Ws1,
                                 bq1, bk1, bv1, bs1, q, k, v, s);
    cudaMemsetAsync(smax, 0, (size_t)Nn * 8 * sizeof(unsigned));
    cudaMemsetAsync(den, 0, (size_t)Nn * 8 * sizeof(float));
    cudaMemsetAsync(agg, 0, (size_t)Nn * DIM * sizeof(float));
    score_kernel<8><<<edgeBlocks, 256>>>(ei, Ee, q, k, ea, We1, be1,
                                         score, smax, 0.25f);
    expsum_kernel<8><<<(Ee * 8 + 255) / 256, 256>>>(ei, Ee, score, smax, den);
    scatter_kernel<8><<<edgeBlocks, 256>>>(ei, Ee, v, ea, We1, be1,
                                           score, den, agg);
    finalize_kernel<true><<<(Nn * DIM + 255) / 256, 256>>>(agg, s, h, Nn * DIM);

    // ---------------- layer 2 (heads=1, C=128) ----------------
    gemm_qkvs<<<gemmGrid, 256>>>(h, Nn, Wq2, Wk2, Wv2, Ws2,
                                 bq2, bk2, bv2, bs2, q, k, v, s);
    cudaMemsetAsync(smax, 0, (size_t)Nn * sizeof(unsigned));
    cudaMemsetAsync(den, 0, (size_t)Nn * sizeof(float));
    cudaMemsetAsync(agg, 0, (size_t)Nn * DIM * sizeof(float));
    score_kernel<1><<<edgeBlocks, 256>>>(ei, Ee, q, k, ea, We2, be2,
                                         score, smax, 0.08838834764831845f);
    expsum_kernel<1><<<(Ee + 255) / 256, 256>>>(ei, Ee, score, smax, den);
    scatter_kernel<1><<<edgeBlocks, 256>>>(ei, Ee, v, ea, We2, be2,
                                           score, den, agg);
    finalize_kernel<false><<<(Nn * DIM + 255) / 256, 256>>>(agg, s, (float*)d_out,
                                                            Nn * DIM);
}

// round 13
// speedup vs baseline: 1.5227x; 1.5227x over previous
#include <cuda_runtime.h>
#include <cuda_bf16.h>
#include <math.h>

#define NMAX 50000
#define EMAX 600000
#define DIM 128

// ---------------- scratch (device globals; no allocations allowed) ----------------
__device__ float g_q[NMAX * DIM];
__device__ float g_k[NMAX * DIM];
__device__ float g_v[NMAX * DIM];
__device__ float g_s[NMAX * DIM];
__device__ float g_h[NMAX * DIM];
__device__ int g_deg[NMAX];
__device__ int g_rowptr[NMAX + 1];
__device__ int g_cursor[NMAX];
__device__ int g_csr_e[EMAX];
__device__ int g_csr_src[EMAX];

// ---------------- node GEMM: out[M,128] = A[M,128] @ W[128,128] + b ----------------
__global__ __launch_bounds__(256) void gemm_qkvs(
    const float* __restrict__ A, int M,
    const float* __restrict__ W0, const float* __restrict__ W1,
    const float* __restrict__ W2, const float* __restrict__ W3,
    const float* __restrict__ b0, const float* __restrict__ b1,
    const float* __restrict__ b2, const float* __restrict__ b3,
    float* __restrict__ o0, float* __restrict__ o1,
    float* __restrict__ o2, float* __restrict__ o3)
{
    const float* W; const float* bias; float* O;
    switch (blockIdx.y) {
        case 0: W = W0; bias = b0; O = o0; break;
        case 1: W = W1; bias = b1; O = o1; break;
        case 2: W = W2; bias = b2; O = o2; break;
        default: W = W3; bias = b3; O = o3; break;
    }
    __shared__ float As[8][128];
    __shared__ float Bs[8][128];
    int tid = threadIdx.x;
    int tx = tid % 16, ty = tid / 16;
    int m0 = blockIdx.x * 128;

    float acc[8][8];
#pragma unroll
    for (int i = 0; i < 8; i++)
#pragma unroll
        for (int j = 0; j < 8; j++) acc[i][j] = 0.f;

    for (int k0 = 0; k0 < 128; k0 += 8) {
        {
            int row_l = tid >> 1;
            int kk = (tid & 1) * 4;
            int row = m0 + row_l;
            float4 av = make_float4(0.f, 0.f, 0.f, 0.f);
            if (row < M) av = *reinterpret_cast<const float4*>(A + (size_t)row * 128 + k0 + kk);
            As[kk + 0][row_l] = av.x;
            As[kk + 1][row_l] = av.y;
            As[kk + 2][row_l] = av.z;
            As[kk + 3][row_l] = av.w;
        }
        {
            float4 bv = *reinterpret_cast<const float4*>(W + (size_t)k0 * 128 + tid * 4);
            int bkk = (tid * 4) >> 7;
            int bn = (tid * 4) & 127;
            Bs[bkk][bn + 0] = bv.x;
            Bs[bkk][bn + 1] = bv.y;
            Bs[bkk][bn + 2] = bv.z;
            Bs[bkk][bn + 3] = bv.w;
        }
        __syncthreads();
#pragma unroll
        for (int kk = 0; kk < 8; kk++) {
            float a[8], b[8];
#pragma unroll
            for (int i = 0; i < 8; i++) a[i] = As[kk][ty * 8 + i];
#pragma unroll
            for (int j = 0; j < 8; j++) b[j] = Bs[kk][tx * 8 + j];
#pragma unroll
            for (int i = 0; i < 8; i++)
#pragma unroll
                for (int j = 0; j < 8; j++) acc[i][j] = fmaf(a[i], b[j], acc[i][j]);
        }
        __syncthreads();
    }
#pragma unroll
    for (int i = 0; i < 8; i++) {
        int row = m0 + ty * 8 + i;
        if (row < M) {
#pragma unroll
            for (int j = 0; j < 8; j++) {
                int col = tx * 8 + j;
                O[(size_t)row * 128 + col] = acc[i][j] + bias[col];
            }
        }
    }
}

// ---------------- CSR build ----------------
__global__ __launch_bounds__(256) void deg_kernel(const int* __restrict__ ei, int E,
                                                  int* __restrict__ deg) {
    int e = blockIdx.x * blockDim.x + threadIdx.x;
    if (e < E) atomicAdd(&deg[ei[E + e]], 1);
}

// single-block 2-pass exclusive scan: each thread sums a contiguous chunk,
// scan the 1024 partials, then write per-element prefixes.
__global__ __launch_bounds__(1024) void scan_kernel(const int* __restrict__ deg,
                                                    int* __restrict__ rowptr,
                                                    int* __restrict__ cursor, int n) {
    __shared__ int sh[1024];
    int tid = threadIdx.x;
    int chunk = (n + 1023) / 1024;
    int start = tid * chunk;
    int end = min(start + chunk, n);
    int sum = 0;
    for (int i = start; i < end; i++) sum += deg[i];
    sh[tid] = sum;
    __syncthreads();
    // inclusive Hillis-Steele over 1024 partials
    for (int ofs = 1; ofs < 1024; ofs <<= 1) {
        int add = (tid >= ofs) ? sh[tid - ofs] : 0;
        __syncthreads();
        sh[tid] += add;
        __syncthreads();
    }
    int base = sh[tid] - sum;  // exclusive prefix of this chunk
    for (int i = start; i < end; i++) {
        rowptr[i] = base;
        cursor[i] = base;
        base += deg[i];
    }
    if (tid == 1023) rowptr[n] = sh[1023];
}

__global__ __launch_bounds__(256) void fill_kernel(const int* __restrict__ ei, int E,
                                                   int* __restrict__ cursor,
                                                   int* __restrict__ csr_e,
                                                   int* __restrict__ csr_src) {
    int e = blockIdx.x * blockDim.x + threadIdx.x;
    if (e >= E) return;
    int dst = ei[E + e];
    int p = atomicAdd(&cursor[dst], 1);
    csr_e[p] = e;
    csr_src[p] = ei[e];
}

// ---------- on-the-fly edge embedding: e_row[lane*4..+3] = ea[e,:16] @ We + be ----------
__device__ __forceinline__ float4 edge_emb(
    const float* __restrict__ ea, int e, int lane,
    const float4* __restrict__ Wes, const float4* __restrict__ bes)
{
    float aval = (lane < 16) ? __ldg(ea + (size_t)e * 16 + lane) : 0.f;
    float4 acc = bes[lane];
#pragma unroll
    for (int j = 0; j < 16; j++) {
        float a = __shfl_sync(0xFFFFFFFFu, aval, j);
        float4 w = Wes[j * 32 + lane];
        acc.x = fmaf(a, w.x, acc.x);
        acc.y = fmaf(a, w.y, acc.y);
        acc.z = fmaf(a, w.z, acc.z);
        acc.w = fmaf(a, w.w, acc.w);
    }
    return acc;
}

__device__ __forceinline__ void load_We(
    const float* __restrict__ We, const float* __restrict__ be,
    float4* Wes, float4* bes, int tid)
{
#pragma unroll
    for (int it = 0; it < 2; it++) {
        int g = tid * 2 + it;
        Wes[g] = reinterpret_cast<const float4*>(We)[g];
    }
    if (tid < 32) bes[tid] = reinterpret_cast<const float4*>(be)[tid];
}

// ---------------- fused per-node attention aggregation (warp per dst node) ----------------
// Online softmax over in-edges; accumulator in registers; no atomics, no score arrays.
template <int H, bool RELU>
__global__ __launch_bounds__(256) void fused_agg(
    const int* __restrict__ rowptr, const int* __restrict__ csr_e,
    const int* __restrict__ csr_src, int Nn,
    const float* __restrict__ q, const float* __restrict__ k,
    const float* __restrict__ v, const float* __restrict__ ea,
    const float* __restrict__ We, const float* __restrict__ be,
    const float* __restrict__ skip, float* __restrict__ out, float scale)
{
    __shared__ float4 Wes[16 * 32];
    __shared__ float4 bes[32];
    int tid = threadIdx.x;
    load_We(We, be, Wes, bes, tid);
    __syncthreads();

    int lane = tid & 31;
    int node = blockIdx.x * 8 + (tid >> 5);
    if (node >= Nn) return;

    int beg = rowptr[node];
    int end = rowptr[node + 1];

    float4 qv = *reinterpret_cast<const float4*>(q + (size_t)node * 128 + lane * 4);
    float m = -1e30f;
    float den = 0.f;
    float4 acc = make_float4(0.f, 0.f, 0.f, 0.f);

    for (int base = beg; base < end; base += 32) {
        int cnt = min(32, end - base);
        int eL = 0, sL = 0;
        if (lane < cnt) {
            eL = csr_e[base + lane];
            sL = csr_src[base + lane];
        }
        for (int j = 0; j < cnt; j++) {
            int e = __shfl_sync(0xFFFFFFFFu, eL, j);
            int src = __shfl_sync(0xFFFFFFFFu, sL, j);
            float4 kv = *reinterpret_cast<const float4*>(k + (size_t)src * 128 + lane * 4);
            float4 vv = *reinterpret_cast<const float4*>(v + (size_t)src * 128 + lane * 4);
            float4 evv = edge_emb(ea, e, lane, Wes, bes);
            float s = qv.x * (kv.x + evv.x) + qv.y * (kv.y + evv.y) +
                      qv.z * (kv.z + evv.z) + qv.w * (kv.w + evv.w);
            s += __shfl_xor_sync(0xFFFFFFFFu, s, 1);
            s += __shfl_xor_sync(0xFFFFFFFFu, s, 2);
            if (H == 1) {
                s += __shfl_xor_sync(0xFFFFFFFFu, s, 4);
                s += __shfl_xor_sync(0xFFFFFFFFu, s, 8);
                s += __shfl_xor_sync(0xFFFFFFFFu, s, 16);
            }
            s *= scale;
            // online softmax update (per 4-lane head group for H=8; whole warp H=1)
            float mnew = fmaxf(m, s);
            float fac = __expf(m - mnew);   // 0 on first edge (m=-1e30)
            float ex = __expf(s - mnew);
            den = den * fac + ex;
            acc.x = acc.x * fac + (vv.x + evv.x) * ex;
            acc.y = acc.y * fac + (vv.y + evv.y) * ex;
            acc.z = acc.z * fac + (vv.z + evv.z) * ex;
            acc.w = acc.w * fac + (vv.w + evv.w) * ex;
            m = mnew;
        }
    }

    float inv = 1.f / (den + 1e-16f);
    float4 sk = *reinterpret_cast<const float4*>(skip + (size_t)node * 128 + lane * 4);
    float4 o;
    o.x = acc.x * inv + sk.x;
    o.y = acc.y * inv + sk.y;
    o.z = acc.z * inv + sk.z;
    o.w = acc.w * inv + sk.w;
    if (RELU) {
        o.x = o.x > 0.f ? o.x : 0.01f * o.x;
        o.y = o.y > 0.f ? o.y : 0.01f * o.y;
        o.z = o.z > 0.f ? o.z : 0.01f * o.z;
        o.w = o.w > 0.f ? o.w : 0.01f * o.w;
    }
    *reinterpret_cast<float4*>(out + (size_t)node * 128 + lane * 4) = o;
}

extern "C" void kernel_launch(void* const* d_in, const int* in_sizes, int n_in,
                              void* d_out, int out_size) {
    const float* x  = (const float*)d_in[0];
    const int*   ei = (const int*)d_in[1];
    const float* ea = (const float*)d_in[2];
    const float* Wq1 = (const float*)d_in[3],  *bq1 = (const float*)d_in[4];
    const float* Wk1 = (const float*)d_in[5],  *bk1 = (const float*)d_in[6];
    const float* Wv1 = (const float*)d_in[7],  *bv1 = (const float*)d_in[8];
    const float* We1 = (const float*)d_in[9],  *be1 = (const float*)d_in[10];
    const float* Ws1 = (const float*)d_in[11], *bs1 = (const float*)d_in[12];
    const float* Wq2 = (const float*)d_in[13], *bq2 = (const float*)d_in[14];
    const float* Wk2 = (const float*)d_in[15], *bk2 = (const float*)d_in[16];
    const float* Wv2 = (const float*)d_in[17], *bv2 = (const float*)d_in[18];
    const float* We2 = (const float*)d_in[19], *be2 = (const float*)d_in[20];
    const float* Ws2 = (const float*)d_in[21], *bs2 = (const float*)d_in[22];

    int Nn = in_sizes[0] / DIM;
    int Ee = in_sizes[1] / 2;

    float *q, *k, *v, *s, *h;
    int *deg, *rowptr, *cursor, *csr_e, *csr_src;
    cudaGetSymbolAddress((void**)&q, g_q);
    cudaGetSymbolAddress((void**)&k, g_k);
    cudaGetSymbolAddress((void**)&v, g_v);
    cudaGetSymbolAddress((void**)&s, g_s);
    cudaGetSymbolAddress((void**)&h, g_h);
    cudaGetSymbolAddress((void**)&deg, g_deg);
    cudaGetSymbolAddress((void**)&rowptr, g_rowptr);
    cudaGetSymbolAddress((void**)&cursor, g_cursor);
    cudaGetSymbolAddress((void**)&csr_e, g_csr_e);
    cudaGetSymbolAddress((void**)&csr_src, g_csr_src);

    dim3 gemmGrid((Nn + 127) / 128, 4);
    int eBlk = (Ee + 255) / 256;
    int nodeBlocks = (Nn + 7) / 8;   // warp per node, 8 warps/block

    // ---------------- CSR build (shared by both layers) ----------------
    cudaMemsetAsync(deg, 0, (size_t)Nn * sizeof(int));
    deg_kernel<<<eBlk, 256>>>(ei, Ee, deg);
    scan_kernel<<<1, 1024>>>(deg, rowptr, cursor, Nn);
    fill_kernel<<<eBlk, 256>>>(ei, Ee, cursor, csr_e, csr_src);

    // ---------------- layer 1 (heads=8, C=16) ----------------
    gemm_qkvs<<<gemmGrid, 256>>>(x, Nn, Wq1, Wk1, Wv1, Ws1,
                                 bq1, bk1, bv1, bs1, q, k, v, s);
    fused_agg<8, true><<<nodeBlocks, 256>>>(rowptr, csr_e, csr_src, Nn,
                                            q, k, v, ea, We1, be1, s, h, 0.25f);

    // ---------------- layer 2 (heads=1, C=128) ----------------
    gemm_qkvs<<<gemmGrid, 256>>>(h, Nn, Wq2, Wk2, Wv2, Ws2,
                                 bq2, bk2, bv2, bs2, q, k, v, s);
    fused_agg<1, false><<<nodeBlocks, 256>>>(rowptr, csr_e, csr_src, Nn,
                                             q, k, v, ea, We2, be2, s, (float*)d_out,
                                             0.08838834764831845f);
}

// round 14
// speedup vs baseline: 2.1384x; 1.4043x over previous
#include <cuda_runtime.h>
#include <cuda_bf16.h>
#include <math.h>

#define NMAX 50000
#define EMAX 600000
#define DIM 128

// ---------------- scratch (device globals; no allocations allowed) ----------------
__device__ float g_q[NMAX * DIM];
__device__ float g_k[NMAX * DIM];
__device__ float g_v[NMAX * DIM];
__device__ float g_s[NMAX * DIM];
__device__ float g_h[NMAX * DIM];
__device__ int g_deg[NMAX];
__device__ int g_rowptr[NMAX + 1];
__device__ int g_cursor[NMAX];
__device__ int g_csr_e[EMAX];
__device__ int g_csr_src[EMAX];

// ---------------- tf32 tensor-core node GEMM ----------------
// out[M,128] = A[M,128] @ W[128,128] + b   (4 weight sets via blockIdx.y)
// 128x128 block tile, 8 warps (2M x 4N), warp = 64x32 via 4x4 m16n8k8 frags.

__device__ __forceinline__ unsigned f2tf32(float f) {
    unsigned u;
    asm("cvt.rna.tf32.f32 %0, %1;" : "=r"(u) : "f"(f));
    return u;
}

__device__ __forceinline__ void mma_tf32(float* d, const unsigned* a, const unsigned* b) {
    asm volatile(
        "mma.sync.aligned.m16n8k8.row.col.f32.tf32.tf32.f32 "
        "{%0,%1,%2,%3}, {%4,%5,%6,%7}, {%8,%9}, {%0,%1,%2,%3};\n"
        : "+f"(d[0]), "+f"(d[1]), "+f"(d[2]), "+f"(d[3])
        : "r"(a[0]), "r"(a[1]), "r"(a[2]), "r"(a[3]), "r"(b[0]), "r"(b[1]));
}

#define KC 32
#define AST 36   // A smem row stride (floats): conflict-free frag reads
#define BST 132  // B smem k-row stride

__global__ __launch_bounds__(256) void gemm_qkvs_mma(
    const float* __restrict__ A, int M,
    const float* __restrict__ W0, const float* __restrict__ W1,
    const float* __restrict__ W2, const float* __restrict__ W3,
    const float* __restrict__ b0, const float* __restrict__ b1,
    const float* __restrict__ b2, const float* __restrict__ b3,
    float* __restrict__ o0, float* __restrict__ o1,
    float* __restrict__ o2, float* __restrict__ o3)
{
    const float* W; const float* bias; float* O;
    switch (blockIdx.y) {
        case 0: W = W0; bias = b0; O = o0; break;
        case 1: W = W1; bias = b1; O = o1; break;
        case 2: W = W2; bias = b2; O = o2; break;
        default: W = W3; bias = b3; O = o3; break;
    }
    __shared__ unsigned As[128 * AST];
    __shared__ unsigned Bs[KC * BST];

    int tid = threadIdx.x;
    int warp = tid >> 5, lane = tid & 31;
    int wm = warp >> 2, wn = warp & 3;       // 2 x 4 warp grid
    int m0 = blockIdx.x * 128;
    int g = lane >> 2;                        // groupID 0..7
    int tg = lane & 3;                        // threadInGroup 0..3

    float acc[4][4][4];
#pragma unroll
    for (int mt = 0; mt < 4; mt++)
#pragma unroll
        for (int nt = 0; nt < 4; nt++)
#pragma unroll
            for (int r = 0; r < 4; r++) acc[mt][nt][r] = 0.f;

    for (int k0 = 0; k0 < 128; k0 += KC) {
        // A tile: 128 rows x KC cols -> As[row*AST + k], tf32-converted
#pragma unroll
        for (int it = 0; it < 4; it++) {
            int f = tid + it * 256;           // float4 id, 0..1023
            int row = f >> 3;                 // 8 float4 per row
            int c4 = (f & 7) * 4;
            float4 av = make_float4(0.f, 0.f, 0.f, 0.f);
            if (m0 + row < M)
                av = *reinterpret_cast<const float4*>(A + (size_t)(m0 + row) * 128 + k0 + c4);
            unsigned* dstp = &As[row * AST + c4];
            dstp[0] = f2tf32(av.x); dstp[1] = f2tf32(av.y);
            dstp[2] = f2tf32(av.z); dstp[3] = f2tf32(av.w);
        }
        // B tile: KC k-rows x 128 cols -> Bs[k*BST + n]
#pragma unroll
        for (int it = 0; it < 4; it++) {
            int f = tid + it * 256;           // 0..1023
            int kr = f >> 5;                  // 32 float4 per k-row
            int c4 = (f & 31) * 4;
            float4 bv = *reinterpret_cast<const float4*>(W + (size_t)(k0 + kr) * 128 + c4);
            unsigned* dstp = &Bs[kr * BST + c4];
            dstp[0] = f2tf32(bv.x); dstp[1] = f2tf32(bv.y);
            dstp[2] = f2tf32(bv.z); dstp[3] = f2tf32(bv.w);
        }
        __syncthreads();

#pragma unroll
        for (int kk = 0; kk < KC / 8; kk++) {
            unsigned afr[4][4];
#pragma unroll
            for (int mt = 0; mt < 4; mt++) {
                int r = wm * 64 + mt * 16 + g;
                int c = kk * 8 + tg;
                afr[mt][0] = As[r * AST + c];
                afr[mt][1] = As[(r + 8) * AST + c];
                afr[mt][2] = As[r * AST + c + 4];
                afr[mt][3] = As[(r + 8) * AST + c + 4];
            }
            unsigned bfr[4][2];
#pragma unroll
            for (int nt = 0; nt < 4; nt++) {
                int kr = kk * 8 + tg;
                int c = wn * 32 + nt * 8 + g;
                bfr[nt][0] = Bs[kr * BST + c];
                bfr[nt][1] = Bs[(kr + 4) * BST + c];
            }
#pragma unroll
            for (int mt = 0; mt < 4; mt++)
#pragma unroll
                for (int nt = 0; nt < 4; nt++)
                    mma_tf32(acc[mt][nt], afr[mt], bfr[nt]);
        }
        __syncthreads();
    }

    // epilogue: add bias, store float2 pairs
#pragma unroll
    for (int mt = 0; mt < 4; mt++) {
        int row0 = m0 + wm * 64 + mt * 16 + g;
#pragma unroll
        for (int nt = 0; nt < 4; nt++) {
            int col = wn * 32 + nt * 8 + 2 * tg;
            float bx = __ldg(bias + col), by = __ldg(bias + col + 1);
            if (row0 < M) {
                float2 v0 = make_float2(acc[mt][nt][0] + bx, acc[mt][nt][1] + by);
                *reinterpret_cast<float2*>(O + (size_t)row0 * 128 + col) = v0;
            }
            if (row0 + 8 < M) {
                float2 v1 = make_float2(acc[mt][nt][2] + bx, acc[mt][nt][3] + by);
                *reinterpret_cast<float2*>(O + (size_t)(row0 + 8) * 128 + col) = v1;
            }
        }
    }
}

// ---------------- CSR build ----------------
__global__ __launch_bounds__(256) void deg_kernel(const int* __restrict__ ei, int E,
                                                  int* __restrict__ deg) {
    int e = blockIdx.x * blockDim.x + threadIdx.x;
    if (e < E) atomicAdd(&deg[ei[E + e]], 1);
}

__global__ __launch_bounds__(1024) void scan_kernel(const int* __restrict__ deg,
                                                    int* __restrict__ rowptr,
                                                    int* __restrict__ cursor, int n) {
    __shared__ int sh[1024];
    int tid = threadIdx.x;
    int chunk = (n + 1023) / 1024;
    int start = tid * chunk;
    int end = min(start + chunk, n);
    int sum = 0;
    for (int i = start; i < end; i++) sum += deg[i];
    sh[tid] = sum;
    __syncthreads();
    for (int ofs = 1; ofs < 1024; ofs <<= 1) {
        int add = (tid >= ofs) ? sh[tid - ofs] : 0;
        __syncthreads();
        sh[tid] += add;
        __syncthreads();
    }
    int base = sh[tid] - sum;
    for (int i = start; i < end; i++) {
        rowptr[i] = base;
        cursor[i] = base;
        base += deg[i];
    }
    if (tid == 1023) rowptr[n] = sh[1023];
}

__global__ __launch_bounds__(256) void fill_kernel(const int* __restrict__ ei, int E,
                                                   int* __restrict__ cursor,
                                                   int* __restrict__ csr_e,
                                                   int* __restrict__ csr_src) {
    int e = blockIdx.x * blockDim.x + threadIdx.x;
    if (e >= E) return;
    int dst = ei[E + e];
    int p = atomicAdd(&cursor[dst], 1);
    csr_e[p] = e;
    csr_src[p] = ei[e];
}

// ---------- on-the-fly edge embedding: e_row[lane*4..+3] = ea[e,:16] @ We + be ----------
__device__ __forceinline__ float4 edge_emb(
    const float* __restrict__ ea, int e, int lane,
    const float4* __restrict__ Wes, const float4* __restrict__ bes)
{
    float aval = (lane < 16) ? __ldg(ea + (size_t)e * 16 + lane) : 0.f;
    float4 acc = bes[lane];
#pragma unroll
    for (int j = 0; j < 16; j++) {
        float a = __shfl_sync(0xFFFFFFFFu, aval, j);
        float4 w = Wes[j * 32 + lane];
        acc.x = fmaf(a, w.x, acc.x);
        acc.y = fmaf(a, w.y, acc.y);
        acc.z = fmaf(a, w.z, acc.z);
        acc.w = fmaf(a, w.w, acc.w);
    }
    return acc;
}

__device__ __forceinline__ void load_We(
    const float* __restrict__ We, const float* __restrict__ be,
    float4* Wes, float4* bes, int tid)
{
#pragma unroll
    for (int it = 0; it < 2; it++) {
        int g = tid * 2 + it;
        Wes[g] = reinterpret_cast<const float4*>(We)[g];
    }
    if (tid < 32) bes[tid] = reinterpret_cast<const float4*>(be)[tid];
}

// ---------------- fused per-node attention aggregation (warp per dst node) ----------------
template <int H, bool RELU>
__global__ __launch_bounds__(256) void fused_agg(
    const int* __restrict__ rowptr, const int* __restrict__ csr_e,
    const int* __restrict__ csr_src, int Nn,
    const float* __restrict__ q, const float* __restrict__ k,
    const float* __restrict__ v, const float* __restrict__ ea,
    const float* __restrict__ We, const float* __restrict__ be,
    const float* __restrict__ skip, float* __restrict__ out, float scale)
{
    __shared__ float4 Wes[16 * 32];
    __shared__ float4 bes[32];
    int tid = threadIdx.x;
    load_We(We, be, Wes, bes, tid);
    __syncthreads();

    int lane = tid & 31;
    int node = blockIdx.x * 8 + (tid >> 5);
    if (node >= Nn) return;

    int beg = rowptr[node];
    int end = rowptr[node + 1];

    float4 qv = *reinterpret_cast<const float4*>(q + (size_t)node * 128 + lane * 4);
    float m = -1e30f;
    float den = 0.f;
    float4 acc = make_float4(0.f, 0.f, 0.f, 0.f);

    for (int base = beg; base < end; base += 32) {
        int cnt = min(32, end - base);
        int eL = 0, sL = 0;
        if (lane < cnt) {
            eL = csr_e[base + lane];
            sL = csr_src[base + lane];
        }
        for (int j = 0; j < cnt; j++) {
            int e = __shfl_sync(0xFFFFFFFFu, eL, j);
            int src = __shfl_sync(0xFFFFFFFFu, sL, j);
            float4 kv = *reinterpret_cast<const float4*>(k + (size_t)src * 128 + lane * 4);
            float4 vv = *reinterpret_cast<const float4*>(v + (size_t)src * 128 + lane * 4);
            float4 evv = edge_emb(ea, e, lane, Wes, bes);
            float s = qv.x * (kv.x + evv.x) + qv.y * (kv.y + evv.y) +
                      qv.z * (kv.z + evv.z) + qv.w * (kv.w + evv.w);
            s += __shfl_xor_sync(0xFFFFFFFFu, s, 1);
            s += __shfl_xor_sync(0xFFFFFFFFu, s, 2);
            if (H == 1) {
                s += __shfl_xor_sync(0xFFFFFFFFu, s, 4);
                s += __shfl_xor_sync(0xFFFFFFFFu, s, 8);
                s += __shfl_xor_sync(0xFFFFFFFFu, s, 16);
            }
            s *= scale;
            float mnew = fmaxf(m, s);
            float fac = __expf(m - mnew);
            float ex = __expf(s - mnew);
            den = den * fac + ex;
            acc.x = acc.x * fac + (vv.x + evv.x) * ex;
            acc.y = acc.y * fac + (vv.y + evv.y) * ex;
            acc.z = acc.z * fac + (vv.z + evv.z) * ex;
            acc.w = acc.w * fac + (vv.w + evv.w) * ex;
            m = mnew;
        }
    }

    float inv = 1.f / (den + 1e-16f);
    float4 sk = *reinterpret_cast<const float4*>(skip + (size_t)node * 128 + lane * 4);
    float4 o;
    o.x = acc.x * inv + sk.x;
    o.y = acc.y * inv + sk.y;
    o.z = acc.z * inv + sk.z;
    o.w = acc.w * inv + sk.w;
    if (RELU) {
        o.x = o.x > 0.f ? o.x : 0.01f * o.x;
        o.y = o.y > 0.f ? o.y : 0.01f * o.y;
        o.z = o.z > 0.f ? o.z : 0.01f * o.z;
        o.w = o.w > 0.f ? o.w : 0.01f * o.w;
    }
    *reinterpret_cast<float4*>(out + (size_t)node * 128 + lane * 4) = o;
}

extern "C" void kernel_launch(void* const* d_in, const int* in_sizes, int n_in,
                              void* d_out, int out_size) {
    const float* x  = (const float*)d_in[0];
    const int*   ei = (const int*)d_in[1];
    const float* ea = (const float*)d_in[2];
    const float* Wq1 = (const float*)d_in[3],  *bq1 = (const float*)d_in[4];
    const float* Wk1 = (const float*)d_in[5],  *bk1 = (const float*)d_in[6];
    const float* Wv1 = (const float*)d_in[7],  *bv1 = (const float*)d_in[8];
    const float* We1 = (const float*)d_in[9],  *be1 = (const float*)d_in[10];
    const float* Ws1 = (const float*)d_in[11], *bs1 = (const float*)d_in[12];
    const float* Wq2 = (const float*)d_in[13], *bq2 = (const float*)d_in[14];
    const float* Wk2 = (const float*)d_in[15], *bk2 = (const float*)d_in[16];
    const float* Wv2 = (const float*)d_in[17], *bv2 = (const float*)d_in[18];
    const float* We2 = (const float*)d_in[19], *be2 = (const float*)d_in[20];
    const float* Ws2 = (const float*)d_in[21], *bs2 = (const float*)d_in[22];

    int Nn = in_sizes[0] / DIM;
    int Ee = in_sizes[1] / 2;

    float *q, *k, *v, *s, *h;
    int *deg, *rowptr, *cursor, *csr_e, *csr_src;
    cudaGetSymbolAddress((void**)&q, g_q);
    cudaGetSymbolAddress((void**)&k, g_k);
    cudaGetSymbolAddress((void**)&v, g_v);
    cudaGetSymbolAddress((void**)&s, g_s);
    cudaGetSymbolAddress((void**)&h, g_h);
    cudaGetSymbolAddress((void**)&deg, g_deg);
    cudaGetSymbolAddress((void**)&rowptr, g_rowptr);
    cudaGetSymbolAddress((void**)&cursor, g_cursor);
    cudaGetSymbolAddress((void**)&csr_e, g_csr_e);
    cudaGetSymbolAddress((void**)&csr_src, g_csr_src);

    dim3 gemmGrid((Nn + 127) / 128, 4);
    int eBlk = (Ee + 255) / 256;
    int nodeBlocks = (Nn + 7) / 8;

    // ---------------- CSR build (shared by both layers) ----------------
    cudaMemsetAsync(deg, 0, (size_t)Nn * sizeof(int));
    deg_kernel<<<eBlk, 256>>>(ei, Ee, deg);
    scan_kernel<<<1, 1024>>>(deg, rowptr, cursor, Nn);
    fill_kernel<<<eBlk, 256>>>(ei, Ee, cursor, csr_e, csr_src);

    // ---------------- layer 1 (heads=8, C=16) ----------------
    gemm_qkvs_mma<<<gemmGrid, 256>>>(x, Nn, Wq1, Wk1, Wv1, Ws1,
                                     bq1, bk1, bv1, bs1, q, k, v, s);
    fused_agg<8, true><<<nodeBlocks, 256>>>(rowptr, csr_e, csr_src, Nn,
                                            q, k, v, ea, We1, be1, s, h, 0.25f);

    // ---------------- layer 2 (heads=1, C=128) ----------------
    gemm_qkvs_mma<<<gemmGrid, 256>>>(h, Nn, Wq2, Wk2, Wv2, Ws2,
                                     bq2, bk2, bv2, bs2, q, k, v, s);
    fused_agg<1, false><<<nodeBlocks, 256>>>(rowptr, csr_e, csr_src, Nn,
                                             q, k, v, ea, We2, be2, s, (float*)d_out,
                                             0.08838834764831845f);
}

// round 16
// speedup vs baseline: 2.2356x; 1.0455x over previous
#include <cuda_runtime.h>
#include <cuda_bf16.h>
#include <math.h>

#define NMAX 50000
#define EMAX 600000
#define DIM 128

// ---------------- scratch (device globals; no allocations allowed) ----------------
__device__ float g_q[NMAX * DIM];
__device__ float g_k[NMAX * DIM];
__device__ float g_v[NMAX * DIM];
__device__ float g_s[NMAX * DIM];
__device__ float g_h[NMAX * DIM];
__device__ float g_ea_csr[(size_t)EMAX * 16];
__device__ int g_deg[NMAX];
__device__ int g_rowptr[NMAX + 1];
__device__ int g_cursor[NMAX];
__device__ int g_csr_e[EMAX];
__device__ int g_csr_src[EMAX];

// ---------------- tf32 tensor-core node GEMM ----------------
__device__ __forceinline__ unsigned f2tf32(float f) {
    unsigned u;
    asm("cvt.rna.tf32.f32 %0, %1;" : "=r"(u) : "f"(f));
    return u;
}

__device__ __forceinline__ void mma_tf32(float* d, const unsigned* a, const unsigned* b) {
    asm volatile(
        "mma.sync.aligned.m16n8k8.row.col.f32.tf32.tf32.f32 "
        "{%0,%1,%2,%3}, {%4,%5,%6,%7}, {%8,%9}, {%0,%1,%2,%3};\n"
        : "+f"(d[0]), "+f"(d[1]), "+f"(d[2]), "+f"(d[3])
        : "r"(a[0]), "r"(a[1]), "r"(a[2]), "r"(a[3]), "r"(b[0]), "r"(b[1]));
}

#define KC 32
#define AST 36
#define BST 132

__global__ __launch_bounds__(256) void gemm_qkvs_mma(
    const float* __restrict__ A, int M,
    const float* __restrict__ W0, const float* __restrict__ W1,
    const float* __restrict__ W2, const float* __restrict__ W3,
    const float* __restrict__ b0, const float* __restrict__ b1,
    const float* __restrict__ b2, const float* __restrict__ b3,
    float* __restrict__ o0, float* __restrict__ o1,
    float* __restrict__ o2, float* __restrict__ o3)
{
    const float* W; const float* bias; float* O;
    switch (blockIdx.y) {
        case 0: W = W0; bias = b0; O = o0; break;
        case 1: W = W1; bias = b1; O = o1; break;
        case 2: W = W2; bias = b2; O = o2; break;
        default: W = W3; bias = b3; O = o3; break;
    }
    __shared__ unsigned As[128 * AST];
    __shared__ unsigned Bs[KC * BST];

    int tid = threadIdx.x;
    int warp = tid >> 5, lane = tid & 31;
    int wm = warp >> 2, wn = warp & 3;
    int m0 = blockIdx.x * 128;
    int g = lane >> 2;
    int tg = lane & 3;

    float acc[4][4][4];
#pragma unroll
    for (int mt = 0; mt < 4; mt++)
#pragma unroll
        for (int nt = 0; nt < 4; nt++)
#pragma unroll
            for (int r = 0; r < 4; r++) acc[mt][nt][r] = 0.f;

    for (int k0 = 0; k0 < 128; k0 += KC) {
#pragma unroll
        for (int it = 0; it < 4; it++) {
            int f = tid + it * 256;
            int row = f >> 3;
            int c4 = (f & 7) * 4;
            float4 av = make_float4(0.f, 0.f, 0.f, 0.f);
            if (m0 + row < M)
                av = *reinterpret_cast<const float4*>(A + (size_t)(m0 + row) * 128 + k0 + c4);
            unsigned* dstp = &As[row * AST + c4];
            dstp[0] = f2tf32(av.x); dstp[1] = f2tf32(av.y);
            dstp[2] = f2tf32(av.z); dstp[3] = f2tf32(av.w);
        }
#pragma unroll
        for (int it = 0; it < 4; it++) {
            int f = tid + it * 256;
            int kr = f >> 5;
            int c4 = (f & 31) * 4;
            float4 bv = *reinterpret_cast<const float4*>(W + (size_t)(k0 + kr) * 128 + c4);
            unsigned* dstp = &Bs[kr * BST + c4];
            dstp[0] = f2tf32(bv.x); dstp[1] = f2tf32(bv.y);
            dstp[2] = f2tf32(bv.z); dstp[3] = f2tf32(bv.w);
        }
        __syncthreads();

#pragma unroll
        for (int kk = 0; kk < KC / 8; kk++) {
            unsigned afr[4][4];
#pragma unroll
            for (int mt = 0; mt < 4; mt++) {
                int r = wm * 64 + mt * 16 + g;
                int c = kk * 8 + tg;
                afr[mt][0] = As[r * AST + c];
                afr[mt][1] = As[(r + 8) * AST + c];
                afr[mt][2] = As[r * AST + c + 4];
                afr[mt][3] = As[(r + 8) * AST + c + 4];
            }
            unsigned bfr[4][2];
#pragma unroll
            for (int nt = 0; nt < 4; nt++) {
                int kr = kk * 8 + tg;
                int c = wn * 32 + nt * 8 + g;
                bfr[nt][0] = Bs[kr * BST + c];
                bfr[nt][1] = Bs[(kr + 4) * BST + c];
            }
#pragma unroll
            for (int mt = 0; mt < 4; mt++)
#pragma unroll
                for (int nt = 0; nt < 4; nt++)
                    mma_tf32(acc[mt][nt], afr[mt], bfr[nt]);
        }
        __syncthreads();
    }

#pragma unroll
    for (int mt = 0; mt < 4; mt++) {
        int row0 = m0 + wm * 64 + mt * 16 + g;
#pragma unroll
        for (int nt = 0; nt < 4; nt++) {
            int col = wn * 32 + nt * 8 + 2 * tg;
            float bx = __ldg(bias + col), by = __ldg(bias + col + 1);
            if (row0 < M) {
                float2 v0 = make_float2(acc[mt][nt][0] + bx, acc[mt][nt][1] + by);
                *reinterpret_cast<float2*>(O + (size_t)row0 * 128 + col) = v0;
            }
            if (row0 + 8 < M) {
                float2 v1 = make_float2(acc[mt][nt][2] + bx, acc[mt][nt][3] + by);
                *reinterpret_cast<float2*>(O + (size_t)(row0 + 8) * 128 + col) = v1;
            }
        }
    }
}

// ---------------- CSR build ----------------
__global__ __launch_bounds__(256) void deg_kernel(const int* __restrict__ ei, int E,
                                                  int* __restrict__ deg) {
    int e = blockIdx.x * blockDim.x + threadIdx.x;
    if (e < E) atomicAdd(&deg[ei[E + e]], 1);
}

__global__ __launch_bounds__(1024) void scan_kernel(const int* __restrict__ deg,
                                                    int* __restrict__ rowptr,
                                                    int* __restrict__ cursor, int n) {
    __shared__ int sh[1024];
    int tid = threadIdx.x;
    int chunk = (n + 1023) / 1024;
    int start = tid * chunk;
    int end = min(start + chunk, n);
    int sum = 0;
    for (int i = start; i < end; i++) sum += deg[i];
    sh[tid] = sum;
    __syncthreads();
    for (int ofs = 1; ofs < 1024; ofs <<= 1) {
        int add = (tid >= ofs) ? sh[tid - ofs] : 0;
        __syncthreads();
        sh[tid] += add;
        __syncthreads();
    }
    int base = sh[tid] - sum;
    for (int i = start; i < end; i++) {
        rowptr[i] = base;
        cursor[i] = base;
        base += deg[i];
    }
    if (tid == 1023) rowptr[n] = sh[1023];
}

__global__ __launch_bounds__(256) void fill_kernel(const int* __restrict__ ei, int E,
                                                   int* __restrict__ cursor,
                                                   int* __restrict__ csr_e,
                                                   int* __restrict__ csr_src) {
    int e = blockIdx.x * blockDim.x + threadIdx.x;
    if (e >= E) return;
    int dst = ei[E + e];
    int p = atomicAdd(&cursor[dst], 1);
    csr_e[p] = e;
    csr_src[p] = ei[e];
}

// reorder ea rows into CSR position order (coalesced writes, random reads)
__global__ __launch_bounds__(256) void reorder_ea_kernel(const int* __restrict__ csr_e,
                                                         const float* __restrict__ ea,
                                                         float* __restrict__ ea_csr, int E) {
    int i = blockIdx.x * blockDim.x + threadIdx.x;  // float4 id
    if (i >= E * 4) return;
    int p = i >> 2, c = i & 3;
    int e = csr_e[p];
    reinterpret_cast<float4*>(ea_csr)[(size_t)p * 4 + c] =
        reinterpret_cast<const float4*>(ea)[(size_t)e * 4 + c];
}

__device__ __forceinline__ void load_We(
    const float* __restrict__ We, const float* __restrict__ be,
    float4* Wes, float4* bes, int tid)
{
#pragma unroll
    for (int it = 0; it < 2; it++) {
        int g = tid * 2 + it;
        Wes[g] = reinterpret_cast<const float4*>(We)[g];
    }
    if (tid < 32) bes[tid] = reinterpret_cast<const float4*>(be)[tid];
}

// ---------------- fused per-node attention (factorized edge embedding) ----------------
// score = q.k[src] + (We^T q).ea[e]   (q.be dropped: softmax-shift-invariant)
// out   = (sum ex*v)/den + We.((sum ex*ea)/den) + be   [be/We terms only if deg>0]
template <int H, bool RELU>
__global__ __launch_bounds__(256) void fused_agg2(
    const int* __restrict__ rowptr, const int* __restrict__ csr_src, int Nn,
    const float* __restrict__ q, const float* __restrict__ k,
    const float* __restrict__ v, const float* __restrict__ ea_csr,
    const float* __restrict__ We, const float* __restrict__ be,
    const float* __restrict__ skip, float* __restrict__ out, float scale)
{
    __shared__ float4 Wes[16 * 32];
    __shared__ float4 bes[32];
    int tid = threadIdx.x;
    load_We(We, be, Wes, bes, tid);
    __syncthreads();

    int lane = tid & 31;
    int node = blockIdx.x * 8 + (tid >> 5);
    if (node >= Nn) return;

    int beg = rowptr[node];
    int end = rowptr[node + 1];
    int t = lane & 3;

    float4 qv = *reinterpret_cast<const float4*>(q + (size_t)node * 128 + lane * 4);

    // prologue: r = We^T q, reduced per head group (H=8) or whole warp (H=1);
    // lane keeps r[4t..4t+3]
    float pj[16];
#pragma unroll
    for (int j = 0; j < 16; j++) {
        float4 w = Wes[j * 32 + lane];
        pj[j] = w.x * qv.x + w.y * qv.y + w.z * qv.z + w.w * qv.w;
    }
#pragma unroll
    for (int j = 0; j < 16; j++) {
        pj[j] += __shfl_xor_sync(0xFFFFFFFFu, pj[j], 1);
        pj[j] += __shfl_xor_sync(0xFFFFFFFFu, pj[j], 2);
        if (H == 1) {
            pj[j] += __shfl_xor_sync(0xFFFFFFFFu, pj[j], 4);
            pj[j] += __shfl_xor_sync(0xFFFFFFFFu, pj[j], 8);
            pj[j] += __shfl_xor_sync(0xFFFFFFFFu, pj[j], 16);
        }
    }
    float4 rk;
    if (t == 0)      rk = make_float4(pj[0],  pj[1],  pj[2],  pj[3]);
    else if (t == 1) rk = make_float4(pj[4],  pj[5],  pj[6],  pj[7]);
    else if (t == 2) rk = make_float4(pj[8],  pj[9],  pj[10], pj[11]);
    else             rk = make_float4(pj[12], pj[13], pj[14], pj[15]);

    float m = -1e30f, den = 0.f;
    float4 accv = make_float4(0.f, 0.f, 0.f, 0.f);
    float4 esum = make_float4(0.f, 0.f, 0.f, 0.f);

    const bool active = (H == 8) || (lane < 4);  // lanes carrying ea slices

    for (int base = beg; base < end; base += 32) {
        int cnt = min(32, end - base);
        int sL = (lane < cnt) ? csr_src[base + lane] : 0;
        for (int j = 0; j < cnt; j++) {
            int src = __shfl_sync(0xFFFFFFFFu, sL, j);
            int idx = base + j;
            float4 kv = *reinterpret_cast<const float4*>(k + (size_t)src * 128 + lane * 4);
            float4 vv = *reinterpret_cast<const float4*>(v + (size_t)src * 128 + lane * 4);
            float4 ev = make_float4(0.f, 0.f, 0.f, 0.f);
            if (active)
                ev = *reinterpret_cast<const float4*>(ea_csr + (size_t)idx * 16 + t * 4);
            float p = kv.x * qv.x + kv.y * qv.y + kv.z * qv.z + kv.w * qv.w;
            if (active)
                p += rk.x * ev.x + rk.y * ev.y + rk.z * ev.z + rk.w * ev.w;
            p += __shfl_xor_sync(0xFFFFFFFFu, p, 1);
            p += __shfl_xor_sync(0xFFFFFFFFu, p, 2);
            if (H == 1) {
                p += __shfl_xor_sync(0xFFFFFFFFu, p, 4);
                p += __shfl_xor_sync(0xFFFFFFFFu, p, 8);
                p += __shfl_xor_sync(0xFFFFFFFFu, p, 16);
            }
            float s = p * scale;
            float mnew = fmaxf(m, s);
            float fac = __expf(m - mnew);
            float ex = __expf(s - mnew);
            den = den * fac + ex;
            accv.x = accv.x * fac + vv.x * ex;
            accv.y = accv.y * fac + vv.y * ex;
            accv.z = accv.z * fac + vv.z * ex;
            accv.w = accv.w * fac + vv.w * ex;
            esum.x = esum.x * fac + ev.x * ex;
            esum.y = esum.y * fac + ev.y * ex;
            esum.z = esum.z * fac + ev.z * ex;
            esum.w = esum.w * fac + ev.w * ex;
            m = mnew;
        }
    }

    float4 sk = *reinterpret_cast<const float4*>(skip + (size_t)node * 128 + lane * 4);
    float4 o = sk;
    if (end > beg) {
        float inv = 1.f / den;  // den >= 1 (max-subtracted)
        esum.x *= inv; esum.y *= inv; esum.z *= inv; esum.w *= inv;
        float4 oc = make_float4(accv.x * inv, accv.y * inv, accv.z * inv, accv.w * inv);
        // oc += We . esum  (esum[j] lives on group lane j>>2 for H=8, lane j>>2 for H=1)
#pragma unroll
        for (int cc = 0; cc < 4; cc++) {
            int srcl = ((H == 8) ? (lane & ~3) : 0) + cc;
            float e0 = __shfl_sync(0xFFFFFFFFu, esum.x, srcl);
            float e1 = __shfl_sync(0xFFFFFFFFu, esum.y, srcl);
            float e2 = __shfl_sync(0xFFFFFFFFu, esum.z, srcl);
            float e3 = __shfl_sync(0xFFFFFFFFu, esum.w, srcl);
            float4 w0 = Wes[(4 * cc + 0) * 32 + lane];
            float4 w1 = Wes[(4 * cc + 1) * 32 + lane];
            float4 w2 = Wes[(4 * cc + 2) * 32 + lane];
            float4 w3 = Wes[(4 * cc + 3) * 32 + lane];
            oc.x += w0.x * e0 + w1.x * e1 + w2.x * e2 + w3.x * e3;
            oc.y += w0.y * e0 + w1.y * e1 + w2.y * e2 + w3.y * e3;
            oc.z += w0.z * e0 + w1.z * e1 + w2.z * e2 + w3.z * e3;
            oc.w += w0.w * e0 + w1.w * e1 + w2.w * e2 + w3.w * e3;
        }
        float4 bb = bes[lane];
        o.x += oc.x + bb.x;
        o.y += oc.y + bb.y;
        o.z += oc.z + bb.z;
        o.w += oc.w + bb.w;
    }
    if (RELU) {
        o.x = o.x > 0.f ? o.x : 0.01f * o.x;
        o.y = o.y > 0.f ? o.y : 0.01f * o.y;
        o.z = o.z > 0.f ? o.z : 0.01f * o.z;
        o.w = o.w > 0.f ? o.w : 0.01f * o.w;
    }
    *reinterpret_cast<float4*>(out + (size_t)node * 128 + lane * 4) = o;
}

extern "C" void kernel_launch(void* const* d_in, const int* in_sizes, int n_in,
                              void* d_out, int out_size) {
    const float* x  = (const float*)d_in[0];
    const int*   ei = (const int*)d_in[1];
    const float* ea = (const float*)d_in[2];
    const float* Wq1 = (const float*)d_in[3],  *bq1 = (const float*)d_in[4];
    const float* Wk1 = (const float*)d_in[5],  *bk1 = (const float*)d_in[6];
    const float* Wv1 = (const float*)d_in[7],  *bv1 = (const float*)d_in[8];
    const float* We1 = (const float*)d_in[9],  *be1 = (const float*)d_in[10];
    const float* Ws1 = (const float*)d_in[11], *bs1 = (const float*)d_in[12];
    const float* Wq2 = (const float*)d_in[13], *bq2 = (const float*)d_in[14];
    const float* Wk2 = (const float*)d_in[15], *bk2 = (const float*)d_in[16];
    const float* Wv2 = (const float*)d_in[17], *bv2 = (const float*)d_in[18];
    const float* We2 = (const float*)d_in[19], *be2 = (const float*)d_in[20];
    const float* Ws2 = (const float*)d_in[21], *bs2 = (const float*)d_in[22];

    int Nn = in_sizes[0] / DIM;
    int Ee = in_sizes[1] / 2;

    float *q, *k, *v, *s, *h, *ea_csr;
    int *deg, *rowptr, *cursor, *csr_e, *csr_src;
    cudaGetSymbolAddress((void**)&q, g_q);
    cudaGetSymbolAddress((void**)&k, g_k);
    cudaGetSymbolAddress((void**)&v, g_v);
    cudaGetSymbolAddress((void**)&s, g_s);
    cudaGetSymbolAddress((void**)&h, g_h);
    cudaGetSymbolAddress((void**)&ea_csr, g_ea_csr);
    cudaGetSymbolAddress((void**)&deg, g_deg);
    cudaGetSymbolAddress((void**)&rowptr, g_rowptr);
    cudaGetSymbolAddress((void**)&cursor, g_cursor);
    cudaGetSymbolAddress((void**)&csr_e, g_csr_e);
    cudaGetSymbolAddress((void**)&csr_src, g_csr_src);

    dim3 gemmGrid((Nn + 127) / 128, 4);
    int eBlk = (Ee + 255) / 256;
    int nodeBlocks = (Nn + 7) / 8;

    // ---------------- CSR build + ea reorder (shared by both layers) ----------------
    cudaMemsetAsync(deg, 0, (size_t)Nn * sizeof(int));
    deg_kernel<<<eBlk, 256>>>(ei, Ee, deg);
    scan_kernel<<<1, 1024>>>(deg, rowptr, cursor, Nn);
    fill_kernel<<<eBlk, 256>>>(ei, Ee, cursor, csr_e, csr_src);
    reorder_ea_kernel<<<(Ee * 4 + 255) / 256, 256>>>(csr_e, ea, ea_csr, Ee);

    // ---------------- layer 1 (heads=8, C=16) ----------------
    gemm_qkvs_mma<<<gemmGrid, 256>>>(x, Nn, Wq1, Wk1, Wv1, Ws1,
                                     bq1, bk1, bv1, bs1, q, k, v, s);
    fused_agg2<8, true><<<nodeBlocks, 256>>>(rowptr, csr_src, Nn,
                                             q, k, v, ea_csr, We1, be1, s, h, 0.25f);

    // ---------------- layer 2 (heads=1, C=128) ----------------
    gemm_qkvs_mma<<<gemmGrid, 256>>>(h, Nn, Wq2, Wk2, Wv2, Ws2,
                                     bq2, bk2, bv2, bs2, q, k, v, s);
    fused_agg2<1, false><<<nodeBlocks, 256>>>(rowptr, csr_src, Nn,
                                              q, k, v, ea_csr, We2, be2, s, (float*)d_out,
                                              0.08838834764831845f);
}